// round 1
// baseline (speedup 1.0000x reference)
#include <cuda_runtime.h>
#include <cuda_bf16.h>

#define Bdim 2048
#define Hdim 1024

// Tile config: 64x64 output tile per CTA, all 4 gates computed together.
// 256 threads (16x16), each thread computes a 4x4 micro-tile for each gate.
#define BM 64
#define BN 64
#define BK 16

__device__ __forceinline__ float sigmoidf_(float x) {
    return 1.0f / (1.0f + expf(-x));
}

__global__ __launch_bounds__(256, 2)
void lstm_fused_kernel(
    const float* __restrict__ X,      // input  [B,H]
    const float* __restrict__ Hin,    // hidden [B,H]
    const float* __restrict__ Cprev,  // pre_cell [B,H]
    const float* __restrict__ wf, const float* __restrict__ wi,
    const float* __restrict__ wo, const float* __restrict__ wc,
    const float* __restrict__ uf, const float* __restrict__ ui,
    const float* __restrict__ uo, const float* __restrict__ uc,
    const float* __restrict__ b1, const float* __restrict__ b2,
    const float* __restrict__ b3, const float* __restrict__ b4,
    const float* __restrict__ mask,   // drop_mask [B,H] (squeezed)
    float* __restrict__ out)          // [2*B*H]: h first, then c
{
    __shared__ float As[BM][BK];          // 4 KB
    __shared__ float Bs[4][BK][BN];       // 16 KB

    const int tx = threadIdx.x;           // 0..15 -> n
    const int ty = threadIdx.y;           // 0..15 -> m
    const int tid = ty * 16 + tx;

    const int bm = blockIdx.y * BM;
    const int bn = blockIdx.x * BN;

    // gate order: f, i, o, c(g)
    const float* Wx[4] = { wf, wi, wo, wc };
    const float* Wh[4] = { uf, ui, uo, uc };

    float acc[4][4][4];
    #pragma unroll
    for (int g = 0; g < 4; ++g)
        #pragma unroll
        for (int i = 0; i < 4; ++i)
            #pragma unroll
            for (int j = 0; j < 4; ++j)
                acc[g][i][j] = 0.0f;

    // A-tile load indices: 64 rows x 16 k = 256 float4, one per thread
    const int a_m  = tid >> 2;        // 0..63
    const int a_k4 = (tid & 3) * 4;   // 0,4,8,12

    // B-tile load indices: per gate 16k x 16 float4, one per thread
    const int b_k  = tid >> 4;        // 0..15
    const int b_n4 = (tid & 15) * 4;  // 0..60

    // K loop: 128 steps of 16; first 64 over input@Wx, then hidden@Wh
    for (int kt = 0; kt < 128; ++kt) {
        const int k0 = (kt & 63) * BK;
        const bool first = (kt < 64);
        const float* Arow = first ? X : Hin;

        // load A tile (coalesced float4, contiguous smem stores)
        {
            float4 av = *reinterpret_cast<const float4*>(
                &Arow[(size_t)(bm + a_m) * Hdim + k0 + a_k4]);
            *reinterpret_cast<float4*>(&As[a_m][a_k4]) = av;
        }
        // load B tiles for all 4 gates
        #pragma unroll
        for (int g = 0; g < 4; ++g) {
            const float* W = first ? Wx[g] : Wh[g];
            float4 bv = *reinterpret_cast<const float4*>(
                &W[(size_t)(k0 + b_k) * Hdim + bn + b_n4]);
            *reinterpret_cast<float4*>(&Bs[g][b_k][b_n4]) = bv;
        }
        __syncthreads();

        #pragma unroll
        for (int kk = 0; kk < BK; ++kk) {
            float a[4];
            #pragma unroll
            for (int i = 0; i < 4; ++i)
                a[i] = As[ty * 4 + i][kk];

            float bf[4][4];
            #pragma unroll
            for (int g = 0; g < 4; ++g)
                *reinterpret_cast<float4*>(bf[g]) =
                    *reinterpret_cast<const float4*>(&Bs[g][kk][tx * 4]);

            #pragma unroll
            for (int g = 0; g < 4; ++g)
                #pragma unroll
                for (int i = 0; i < 4; ++i)
                    #pragma unroll
                    for (int j = 0; j < 4; ++j)
                        acc[g][i][j] = fmaf(a[i], bf[g][j], acc[g][i][j]);
        }
        __syncthreads();
    }

    // Epilogue: f=sig(.+b1), i=sig(.+b2), o=sig(.+b3), g=tanh(.+b4)
    // c = cprev*f + i*g ; h = o*tanh(c)*mask
    #pragma unroll
    for (int i = 0; i < 4; ++i) {
        const int row = bm + ty * 4 + i;
        const size_t rbase = (size_t)row * Hdim;
        #pragma unroll
        for (int j = 0; j < 4; ++j) {
            const int col = bn + tx * 4 + j;
            float fg = sigmoidf_(acc[0][i][j] + b1[col]);
            float ig = sigmoidf_(acc[1][i][j] + b2[col]);
            float og = sigmoidf_(acc[2][i][j] + b3[col]);
            float gg = tanhf(acc[3][i][j] + b4[col]);
            float c  = Cprev[rbase + col] * fg + ig * gg;
            float h  = og * tanhf(c) * mask[rbase + col];
            out[rbase + col] = h;
            out[(size_t)Bdim * Hdim + rbase + col] = c;
        }
    }
}

extern "C" void kernel_launch(void* const* d_in, const int* in_sizes, int n_in,
                              void* d_out, int out_size) {
    const float* X     = (const float*)d_in[0];   // input
    const float* Hin   = (const float*)d_in[1];   // hidden
    const float* Cprev = (const float*)d_in[2];   // pre_cell
    const float* wi    = (const float*)d_in[3];
    const float* wf    = (const float*)d_in[4];
    const float* wo    = (const float*)d_in[5];
    const float* wc    = (const float*)d_in[6];
    const float* ui    = (const float*)d_in[7];
    const float* uf    = (const float*)d_in[8];
    const float* uo    = (const float*)d_in[9];
    const float* uc    = (const float*)d_in[10];
    const float* b1    = (const float*)d_in[11];
    const float* b2    = (const float*)d_in[12];
    const float* b3    = (const float*)d_in[13];
    const float* b4    = (const float*)d_in[14];
    const float* mask  = (const float*)d_in[15];

    float* out = (float*)d_out;

    dim3 block(16, 16);
    dim3 grid(Hdim / BN, Bdim / BM);   // (16, 32) = 512 CTAs
    lstm_fused_kernel<<<grid, block>>>(
        X, Hin, Cprev,
        wf, wi, wo, wc,
        uf, ui, uo, uc,
        b1, b2, b3, b4,
        mask, out);
}

// round 3
// speedup vs baseline: 2.4587x; 2.4587x over previous
#include <cuda_runtime.h>
#include <cuda_bf16.h>
#include <cstdint>

#define Bsz 2048
#define Hsz 1024
#define Ktot 2048           // input K (1024) + hidden K (1024)
#define Ntot 4096           // 4 gates * 1024

// ---------------- scratch (static device memory; no allocs) ----------------
__device__ unsigned short g_Ahi[Bsz * Ktot];            // 8 MB
__device__ unsigned short g_Alo[Bsz * Ktot];            // 8 MB
__device__ unsigned short g_Bhi[(size_t)Ntot * Ktot];   // 16 MB
__device__ unsigned short g_Blo[(size_t)Ntot * Ktot];   // 16 MB
__device__ float          g_gates[(size_t)Bsz * Ntot];  // 32 MB

// ---------------- helpers ----------------
__device__ __forceinline__ uint32_t smem_u32(const void* p) {
    uint32_t a;
    asm("{ .reg .u64 t; cvta.to.shared.u64 t, %1; cvt.u32.u64 %0, t; }" : "=r"(a) : "l"(p));
    return a;
}
__device__ __forceinline__ void cp_async16(uint32_t dst, const void* src) {
    asm volatile("cp.async.cg.shared.global [%0], [%1], 16;" :: "r"(dst), "l"(src) : "memory");
}
#define CP_COMMIT() asm volatile("cp.async.commit_group;" ::: "memory")
#define CP_WAIT2()  asm volatile("cp.async.wait_group 2;" ::: "memory")

__device__ __forceinline__ void ldsm4(uint32_t& r0, uint32_t& r1, uint32_t& r2, uint32_t& r3,
                                      uint32_t addr) {
    asm volatile("ldmatrix.sync.aligned.m8n8.x4.shared.b16 {%0,%1,%2,%3}, [%4];"
                 : "=r"(r0), "=r"(r1), "=r"(r2), "=r"(r3) : "r"(addr));
}
__device__ __forceinline__ void mma16816(float* d, const uint32_t* a, const uint32_t* b) {
    asm volatile(
        "mma.sync.aligned.m16n8k16.row.col.f32.bf16.bf16.f32 "
        "{%0,%1,%2,%3}, {%4,%5,%6,%7}, {%8,%9}, {%0,%1,%2,%3};"
        : "+f"(d[0]), "+f"(d[1]), "+f"(d[2]), "+f"(d[3])
        : "r"(a[0]), "r"(a[1]), "r"(a[2]), "r"(a[3]), "r"(b[0]), "r"(b[1]));
}

__device__ __forceinline__ void split_bf16(float x, unsigned short& h, unsigned short& l) {
    __nv_bfloat16 hb = __float2bfloat16_rn(x);
    float hf = __bfloat162float(hb);
    __nv_bfloat16 lb = __float2bfloat16_rn(x - hf);
    h = __bfloat16_as_ushort(hb);
    l = __bfloat16_as_ushort(lb);
}

// ---------------- 1) convert A: [input | hidden] -> bf16 hi/lo ----------------
__global__ void conv_a_kernel(const float* __restrict__ X, const float* __restrict__ Hn) {
    int idx = blockIdx.x * blockDim.x + threadIdx.x;     // one float4
    int e0   = idx * 4;
    int col4 = e0 & (Ktot - 1);
    int row  = e0 >> 11;
    const float* src = (col4 < Hsz) ? &X[row * Hsz + col4] : &Hn[row * Hsz + col4 - Hsz];
    float4 v = *reinterpret_cast<const float4*>(src);
    float vv[4] = {v.x, v.y, v.z, v.w};
    unsigned short h[4], l[4];
#pragma unroll
    for (int i = 0; i < 4; ++i) split_bf16(vv[i], h[i], l[i]);
    *reinterpret_cast<uint2*>(&g_Ahi[e0]) = *reinterpret_cast<uint2*>(h);
    *reinterpret_cast<uint2*>(&g_Alo[e0]) = *reinterpret_cast<uint2*>(l);
}

// ---------------- 2) transpose + convert weights -> B [Ntot, Ktot] hi/lo ------
__global__ void conv_b_kernel(const float* wf, const float* wi, const float* wo, const float* wc,
                              const float* uf, const float* ui, const float* uo, const float* uc) {
    __shared__ float tile[32][33];
    const float* srcs[8] = {wf, wi, wo, wc, uf, ui, uo, uc};
    int k0 = blockIdx.x * 32;          // 0..2047
    int n0 = blockIdx.y * 32;          // 0..4095
    int g  = n0 >> 10;
    const float* W = srcs[(k0 < Hsz ? 0 : 4) + g];
    int kk = k0 & (Hsz - 1);
    int nn = n0 & (Hsz - 1);
    int tx = threadIdx.x, ty = threadIdx.y;  // 32 x 8
#pragma unroll
    for (int j = 0; j < 4; ++j)
        tile[ty + j * 8][tx] = W[(size_t)(kk + ty + j * 8) * Hsz + nn + tx];
    __syncthreads();
#pragma unroll
    for (int j = 0; j < 4; ++j) {
        int n = n0 + ty + j * 8;
        int k = k0 + tx;
        unsigned short h, l;
        split_bf16(tile[tx][ty + j * 8], h, l);
        g_Bhi[(size_t)n * Ktot + k] = h;
        g_Blo[(size_t)n * Ktot + k] = l;
    }
}

// ---------------- 3) mma.sync GEMM: gates = A @ B^T (3 split passes) ----------
#define BM 128
#define BN 256
#define BK 32
#define NSTAGE 4
#define A_ST_BYTES (BM * BK * 2)             // 8192
#define B_ST_BYTES (BN * BK * 2)             // 16384
#define STAGE_BYTES (A_ST_BYTES + B_ST_BYTES)
#define GEMM_SMEM (NSTAGE * STAGE_BYTES)     // 98304
#define NCHUNK 192                            // 3 splits * (2048/32)

// smem rows are 64B (32 bf16); 16B-chunk swizzle keeps cp.async stores and
// ldmatrix reads bank-conflict-free: chunk ^= (row>>1)&3
__device__ __forceinline__ uint32_t swz(uint32_t base, int r, int c) {
    return base + r * 64 + (((uint32_t)(c ^ ((r >> 1) & 3))) << 4);
}

__global__ void __launch_bounds__(512, 1)
gemm_kernel() {
    extern __shared__ char smem[];
    const uint32_t sb = smem_u32(smem);
    const int tid  = threadIdx.x;
    const int wid  = tid >> 5;
    const int lane = tid & 31;
    const int wm = wid >> 3;       // 0..1  (M)
    const int wn = wid & 7;        // 0..7  (N)
    const int bm = blockIdx.y * BM;
    const int bn = blockIdx.x * BN;

    const char* Apass[3] = {(const char*)g_Ahi, (const char*)g_Ahi, (const char*)g_Alo};
    const char* Bpass[3] = {(const char*)g_Bhi, (const char*)g_Blo, (const char*)g_Bhi};

    float acc[4][4][4];
#pragma unroll
    for (int mf = 0; mf < 4; ++mf)
#pragma unroll
        for (int nf = 0; nf < 4; ++nf)
#pragma unroll
            for (int r = 0; r < 4; ++r) acc[mf][nf][r] = 0.0f;

    // load indices: A 512 x 16B chunks (1/thread), B 1024 (2/thread)
    const int ar = tid >> 2, ac = tid & 3;
    const int br0 = tid >> 2, bc0 = tid & 3;           // g = tid
    const int br1 = (tid + 512) >> 2, bc1 = tid & 3;   // g = tid + 512

    auto load_chunk = [&](int c) {
        const int p  = c >> 6;
        const int kc = c & 63;
        const uint32_t st = (uint32_t)(c & (NSTAGE - 1)) * STAGE_BYTES;
        const uint32_t sA = sb + st;
        const uint32_t sB = sA + A_ST_BYTES;
        const char* Ag = Apass[p] + ((size_t)bm * Ktot + (size_t)kc * BK) * 2;
        const char* Bg = Bpass[p] + ((size_t)bn * Ktot + (size_t)kc * BK) * 2;
        cp_async16(swz(sA, ar, ac),  Ag + (size_t)ar  * (Ktot * 2) + ac  * 16);
        cp_async16(swz(sB, br0, bc0), Bg + (size_t)br0 * (Ktot * 2) + bc0 * 16);
        cp_async16(swz(sB, br1, bc1), Bg + (size_t)br1 * (Ktot * 2) + bc1 * 16);
        CP_COMMIT();
    };

    load_chunk(0); load_chunk(1); load_chunk(2);

    // per-lane ldmatrix row components
    const int a_row = wm * 64 + (lane & 15);           // + mf*16
    const int a_cb  = (lane >> 4) & 1;                 // k chunk bit
    const int b_row = wn * 32 + ((lane >> 4) & 1) * 8 + (lane & 7);  // + nfp*16
    const int b_cb  = (lane >> 3) & 1;

    for (int c = 0; c < NCHUNK; ++c) {
        CP_WAIT2();
        __syncthreads();
        const uint32_t st = (uint32_t)(c & (NSTAGE - 1)) * STAGE_BYTES;
        const uint32_t sA = sb + st;
        const uint32_t sB = sA + A_ST_BYTES;

#pragma unroll
        for (int ks = 0; ks < 2; ++ks) {
            uint32_t af[4][4];
#pragma unroll
            for (int mf = 0; mf < 4; ++mf)
                ldsm4(af[mf][0], af[mf][1], af[mf][2], af[mf][3],
                      swz(sA, a_row + mf * 16, ks * 2 + a_cb));
            uint32_t bf[2][4];
#pragma unroll
            for (int nfp = 0; nfp < 2; ++nfp)
                ldsm4(bf[nfp][0], bf[nfp][1], bf[nfp][2], bf[nfp][3],
                      swz(sB, b_row + nfp * 16, ks * 2 + b_cb));
#pragma unroll
            for (int mf = 0; mf < 4; ++mf)
#pragma unroll
                for (int nf = 0; nf < 4; ++nf)
                    mma16816(acc[mf][nf], af[mf], &bf[nf >> 1][(nf & 1) * 2]);
        }
        __syncthreads();
        if (c + NSTAGE - 1 < NCHUNK) load_chunk(c + NSTAGE - 1);
        else CP_COMMIT();    // empty group keeps wait_group 2 semantics uniform
    }

    // write accumulators -> g_gates
    const int grp = lane >> 2, tig = lane & 3;
#pragma unroll
    for (int mf = 0; mf < 4; ++mf) {
        const int r0 = bm + wm * 64 + mf * 16 + grp;
#pragma unroll
        for (int nf = 0; nf < 4; ++nf) {
            const int col = bn + wn * 32 + nf * 8 + tig * 2;
            *reinterpret_cast<float2*>(&g_gates[(size_t)r0 * Ntot + col]) =
                make_float2(acc[mf][nf][0], acc[mf][nf][1]);
            *reinterpret_cast<float2*>(&g_gates[(size_t)(r0 + 8) * Ntot + col]) =
                make_float2(acc[mf][nf][2], acc[mf][nf][3]);
        }
    }
}

// ---------------- 4) LSTM elementwise epilogue ----------------
__device__ __forceinline__ float sigmoidf_(float x) { return 1.0f / (1.0f + expf(-x)); }

__global__ void lstm_ep_kernel(const float* __restrict__ Cprev, const float* __restrict__ mask,
                               const float* __restrict__ b1, const float* __restrict__ b2,
                               const float* __restrict__ b3, const float* __restrict__ b4,
                               float* __restrict__ out) {
    int idx = blockIdx.x * blockDim.x + threadIdx.x;   // one float4 of H
    int e0   = idx * 4;
    int col4 = e0 & (Hsz - 1);
    int row  = e0 >> 10;
    const float* gr = &g_gates[(size_t)row * Ntot];
    float4 fv = *reinterpret_cast<const float4*>(&gr[col4]);
    float4 iv = *reinterpret_cast<const float4*>(&gr[Hsz + col4]);
    float4 ov = *reinterpret_cast<const float4*>(&gr[2 * Hsz + col4]);
    float4 gv = *reinterpret_cast<const float4*>(&gr[3 * Hsz + col4]);
    float4 cp = *reinterpret_cast<const float4*>(&Cprev[row * Hsz + col4]);
    float4 mk = *reinterpret_cast<const float4*>(&mask[row * Hsz + col4]);
    float4 B1 = *reinterpret_cast<const float4*>(&b1[col4]);
    float4 B2 = *reinterpret_cast<const float4*>(&b2[col4]);
    float4 B3 = *reinterpret_cast<const float4*>(&b3[col4]);
    float4 B4 = *reinterpret_cast<const float4*>(&b4[col4]);

    float f[4] = {fv.x, fv.y, fv.z, fv.w}, i_[4] = {iv.x, iv.y, iv.z, iv.w};
    float o[4] = {ov.x, ov.y, ov.z, ov.w}, g[4] = {gv.x, gv.y, gv.z, gv.w};
    float c0[4] = {cp.x, cp.y, cp.z, cp.w}, m[4] = {mk.x, mk.y, mk.z, mk.w};
    float bb1[4] = {B1.x, B1.y, B1.z, B1.w}, bb2[4] = {B2.x, B2.y, B2.z, B2.w};
    float bb3[4] = {B3.x, B3.y, B3.z, B3.w}, bb4[4] = {B4.x, B4.y, B4.z, B4.w};

    float hv[4], cv[4];
#pragma unroll
    for (int j = 0; j < 4; ++j) {
        float ft = sigmoidf_(f[j] + bb1[j]);
        float it = sigmoidf_(i_[j] + bb2[j]);
        float ot = sigmoidf_(o[j] + bb3[j]);
        float gt = tanhf(g[j] + bb4[j]);
        float ct = c0[j] * ft + it * gt;
        hv[j] = ot * tanhf(ct) * m[j];
        cv[j] = ct;
    }
    *reinterpret_cast<float4*>(&out[(size_t)row * Hsz + col4]) =
        make_float4(hv[0], hv[1], hv[2], hv[3]);
    *reinterpret_cast<float4*>(&out[(size_t)Bsz * Hsz + (size_t)row * Hsz + col4]) =
        make_float4(cv[0], cv[1], cv[2], cv[3]);
}

// ---------------- launch ----------------
extern "C" void kernel_launch(void* const* d_in, const int* in_sizes, int n_in,
                              void* d_out, int out_size) {
    const float* X     = (const float*)d_in[0];
    const float* Hn    = (const float*)d_in[1];
    const float* Cprev = (const float*)d_in[2];
    const float* wi    = (const float*)d_in[3];
    const float* wf    = (const float*)d_in[4];
    const float* wo    = (const float*)d_in[5];
    const float* wc    = (const float*)d_in[6];
    const float* ui    = (const float*)d_in[7];
    const float* uf    = (const float*)d_in[8];
    const float* uo    = (const float*)d_in[9];
    const float* uc    = (const float*)d_in[10];
    const float* b1    = (const float*)d_in[11];
    const float* b2    = (const float*)d_in[12];
    const float* b3    = (const float*)d_in[13];
    const float* b4    = (const float*)d_in[14];
    const float* mask  = (const float*)d_in[15];
    float* out = (float*)d_out;

    // 1) convert activations
    conv_a_kernel<<<(Bsz * Ktot / 4) / 256, 256>>>(X, Hn);
    // 2) transpose + convert weights
    dim3 tb(32, 8);
    dim3 tg(Ktot / 32, Ntot / 32);
    conv_b_kernel<<<tg, tb>>>(wf, wi, wo, wc, uf, ui, uo, uc);
    // 3) GEMM (tensor cores via mma.sync)
    static bool attr_set = false;
    if (!attr_set) {
        cudaFuncSetAttribute(gemm_kernel, cudaFuncAttributeMaxDynamicSharedMemorySize, GEMM_SMEM);
        attr_set = true;
    }
    dim3 gg(Ntot / BN, Bsz / BM);    // (16, 16)
    gemm_kernel<<<gg, 512, GEMM_SMEM>>>();
    // 4) LSTM epilogue
    lstm_ep_kernel<<<(Bsz * Hsz / 4) / 256, 256>>>(Cprev, mask, b1, b2, b3, b4, out);
}

// round 4
// speedup vs baseline: 4.0501x; 1.6472x over previous
#include <cuda_runtime.h>
#include <cuda_fp16.h>
#include <cstdint>

#define Bsz 2048
#define Hsz 1024
#define Ktot 2048           // input K (1024) + hidden K (1024)
#define Ntot 4096           // 4 gates * 1024 (gate-interleaved bands of 32)

// ---------------- scratch (static device memory; no allocs) ----------------
__device__ unsigned short g_Ah[Bsz * Ktot];             // 8 MB  (fp16 hi)
__device__ unsigned short g_Al[Bsz * Ktot];             // 8 MB  (fp16 lo)
__device__ unsigned short g_B [(size_t)Ntot * Ktot];    // 16 MB (fp16, [n'][k])

// ---------------- helpers ----------------
__device__ __forceinline__ uint32_t smem_u32(const void* p) {
    uint32_t a;
    asm("{ .reg .u64 t; cvta.to.shared.u64 t, %1; cvt.u32.u64 %0, t; }" : "=r"(a) : "l"(p));
    return a;
}
__device__ __forceinline__ void cp_async16(uint32_t dst, const void* src) {
    asm volatile("cp.async.cg.shared.global [%0], [%1], 16;" :: "r"(dst), "l"(src) : "memory");
}
#define CP_COMMIT() asm volatile("cp.async.commit_group;" ::: "memory")
#define CP_WAIT2()  asm volatile("cp.async.wait_group 2;" ::: "memory")

__device__ __forceinline__ void ldsm4(uint32_t& r0, uint32_t& r1, uint32_t& r2, uint32_t& r3,
                                      uint32_t addr) {
    asm volatile("ldmatrix.sync.aligned.m8n8.x4.shared.b16 {%0,%1,%2,%3}, [%4];"
                 : "=r"(r0), "=r"(r1), "=r"(r2), "=r"(r3) : "r"(addr));
}
__device__ __forceinline__ void mma16816(float* d, const uint32_t* a, const uint32_t* b) {
    asm volatile(
        "mma.sync.aligned.m16n8k16.row.col.f32.f16.f16.f32 "
        "{%0,%1,%2,%3}, {%4,%5,%6,%7}, {%8,%9}, {%0,%1,%2,%3};"
        : "+f"(d[0]), "+f"(d[1]), "+f"(d[2]), "+f"(d[3])
        : "r"(a[0]), "r"(a[1]), "r"(a[2]), "r"(a[3]), "r"(b[0]), "r"(b[1]));
}

__device__ __forceinline__ void split_fp16(float x, unsigned short& h, unsigned short& l) {
    __half hb = __float2half_rn(x);
    float hf = __half2float(hb);
    __half lb = __float2half_rn(x - hf);
    h = __half_as_ushort(hb);
    l = __half_as_ushort(lb);
}

// ---------------- 1) convert A: [input | hidden] -> fp16 hi/lo ----------------
__global__ void conv_a_kernel(const float* __restrict__ X, const float* __restrict__ Hn) {
    int idx = blockIdx.x * blockDim.x + threadIdx.x;     // one float4
    int e0   = idx * 4;
    int col4 = e0 & (Ktot - 1);
    int row  = e0 >> 11;
    const float* src = (col4 < Hsz) ? &X[row * Hsz + col4] : &Hn[row * Hsz + col4 - Hsz];
    float4 v = *reinterpret_cast<const float4*>(src);
    float vv[4] = {v.x, v.y, v.z, v.w};
    unsigned short h[4], l[4];
#pragma unroll
    for (int i = 0; i < 4; ++i) split_fp16(vv[i], h[i], l[i]);
    *reinterpret_cast<uint2*>(&g_Ah[e0]) = *reinterpret_cast<uint2*>(h);
    *reinterpret_cast<uint2*>(&g_Al[e0]) = *reinterpret_cast<uint2*>(l);
}

// ------ 2) transpose + convert weights -> B [n'][k] fp16, gate-interleaved ----
// n' = (j>>3)*32 + g*8 + (j&7)   for original gate g, hidden col j
__global__ void conv_b_kernel(const float* wf, const float* wi, const float* wo, const float* wc,
                              const float* uf, const float* ui, const float* uo, const float* uc) {
    __shared__ float tile[32][33];
    const float* srcs[8] = {wf, wi, wo, wc, uf, ui, uo, uc};
    int k0 = blockIdx.x * 32;          // 0..2047
    int n0 = blockIdx.y * 32;          // 0..4095 (original gate-major space)
    int g  = n0 >> 10;
    const float* W = srcs[(k0 < Hsz ? 0 : 4) + g];
    int kk = k0 & (Hsz - 1);
    int nn = n0 & (Hsz - 1);
    int tx = threadIdx.x, ty = threadIdx.y;  // 32 x 8
#pragma unroll
    for (int j2 = 0; j2 < 4; ++j2)
        tile[ty + j2 * 8][tx] = W[(size_t)(kk + ty + j2 * 8) * Hsz + nn + tx];
    __syncthreads();
#pragma unroll
    for (int j2 = 0; j2 < 4; ++j2) {
        int n = n0 + ty + j2 * 8;       // original col
        int j = n & (Hsz - 1);          // hidden col
        int np = ((j >> 3) << 5) + (g << 3) + (j & 7);
        int k = k0 + tx;
        __half hv = __float2half_rn(tile[tx][ty + j2 * 8]);
        g_B[(size_t)np * Ktot + k] = __half_as_ushort(hv);
    }
}

// ------ 3) mma.sync GEMM + fused LSTM epilogue ------
#define BM 128
#define BN 256
#define BK 32
#define NSTAGE 4
#define AH_BYTES (BM * BK * 2)               // 8192
#define B_ST_BYTES (BN * BK * 2)             // 16384
#define STAGE_BYTES (2 * AH_BYTES + B_ST_BYTES)   // 32768
#define GEMM_SMEM (NSTAGE * STAGE_BYTES)     // 131072
#define NCHUNK 64                             // 2048 / 32

__device__ __forceinline__ uint32_t swz(uint32_t base, int r, int c) {
    return base + r * 64 + (((uint32_t)(c ^ ((r >> 1) & 3))) << 4);
}
__device__ __forceinline__ float sigmoidf_(float x) { return 1.0f / (1.0f + expf(-x)); }

__global__ void __launch_bounds__(512, 1)
gemm_kernel(const float* __restrict__ Cprev, const float* __restrict__ mask,
            const float* __restrict__ b1, const float* __restrict__ b2,
            const float* __restrict__ b3, const float* __restrict__ b4,
            float* __restrict__ out) {
    extern __shared__ char smem[];
    const uint32_t sb = smem_u32(smem);
    const int tid  = threadIdx.x;
    const int wid  = tid >> 5;
    const int lane = tid & 31;
    const int wm = wid >> 3;       // 0..1  (M)
    const int wn = wid & 7;        // 0..7  (N)
    const int bm = blockIdx.y * BM;
    const int bn = blockIdx.x * BN;

    float acc[4][4][4];
#pragma unroll
    for (int mf = 0; mf < 4; ++mf)
#pragma unroll
        for (int nf = 0; nf < 4; ++nf)
#pragma unroll
            for (int r = 0; r < 4; ++r) acc[mf][nf][r] = 0.0f;

    // load indices (16B chunks): Ah 512, Al 512, B 1024 -> 4 per thread
    const int ar = tid >> 2, ac = tid & 3;
    const int br0 = tid >> 2, bc0 = tid & 3;
    const int br1 = (tid + 512) >> 2, bc1 = tid & 3;

    auto load_chunk = [&](int c) {
        const uint32_t st = (uint32_t)(c & (NSTAGE - 1)) * STAGE_BYTES;
        const uint32_t sAh = sb + st;
        const uint32_t sAl = sAh + AH_BYTES;
        const uint32_t sB  = sAl + AH_BYTES;
        const char* Ahg = (const char*)g_Ah + ((size_t)bm * Ktot + (size_t)c * BK) * 2;
        const char* Alg = (const char*)g_Al + ((size_t)bm * Ktot + (size_t)c * BK) * 2;
        const char* Bg  = (const char*)g_B  + ((size_t)bn * Ktot + (size_t)c * BK) * 2;
        cp_async16(swz(sAh, ar, ac),  Ahg + (size_t)ar  * (Ktot * 2) + ac  * 16);
        cp_async16(swz(sAl, ar, ac),  Alg + (size_t)ar  * (Ktot * 2) + ac  * 16);
        cp_async16(swz(sB, br0, bc0), Bg  + (size_t)br0 * (Ktot * 2) + bc0 * 16);
        cp_async16(swz(sB, br1, bc1), Bg  + (size_t)br1 * (Ktot * 2) + bc1 * 16);
        CP_COMMIT();
    };

    load_chunk(0); load_chunk(1); load_chunk(2);

    const int a_row = wm * 64 + (lane & 15);
    const int a_cb  = (lane >> 4) & 1;
    const int b_row = wn * 32 + ((lane >> 4) & 1) * 8 + (lane & 7);
    const int b_cb  = (lane >> 3) & 1;

    for (int c = 0; c < NCHUNK; ++c) {
        CP_WAIT2();
        __syncthreads();
        const uint32_t st = (uint32_t)(c & (NSTAGE - 1)) * STAGE_BYTES;
        const uint32_t sAh = sb + st;
        const uint32_t sAl = sAh + AH_BYTES;
        const uint32_t sB  = sAl + AH_BYTES;

#pragma unroll
        for (int ks = 0; ks < 2; ++ks) {
            uint32_t bf[2][4];
#pragma unroll
            for (int nfp = 0; nfp < 2; ++nfp)
                ldsm4(bf[nfp][0], bf[nfp][1], bf[nfp][2], bf[nfp][3],
                      swz(sB, b_row + nfp * 16, ks * 2 + b_cb));
            uint32_t af[4][4];
#pragma unroll
            for (int mf = 0; mf < 4; ++mf)
                ldsm4(af[mf][0], af[mf][1], af[mf][2], af[mf][3],
                      swz(sAh, a_row + mf * 16, ks * 2 + a_cb));
#pragma unroll
            for (int mf = 0; mf < 4; ++mf)
#pragma unroll
                for (int nf = 0; nf < 4; ++nf)
                    mma16816(acc[mf][nf], af[mf], &bf[nf >> 1][(nf & 1) * 2]);
#pragma unroll
            for (int mf = 0; mf < 4; ++mf)
                ldsm4(af[mf][0], af[mf][1], af[mf][2], af[mf][3],
                      swz(sAl, a_row + mf * 16, ks * 2 + a_cb));
#pragma unroll
            for (int mf = 0; mf < 4; ++mf)
#pragma unroll
                for (int nf = 0; nf < 4; ++nf)
                    mma16816(acc[mf][nf], af[mf], &bf[nf >> 1][(nf & 1) * 2]);
        }
        __syncthreads();
        if (c + NSTAGE - 1 < NCHUNK) load_chunk(c + NSTAGE - 1);
        else CP_COMMIT();
    }

    // ---- fused LSTM epilogue ----
    // warp band: n' in [bn + wn*32, +32) -> hidden octet j0, gates = nf
    const int grp = lane >> 2, tig = lane & 3;
    const int j0 = ((bn >> 5) + wn) * 8 + tig * 2;   // hidden col of acc pair
    const float2 B1 = *reinterpret_cast<const float2*>(&b1[j0]);
    const float2 B2 = *reinterpret_cast<const float2*>(&b2[j0]);
    const float2 B3 = *reinterpret_cast<const float2*>(&b3[j0]);
    const float2 B4 = *reinterpret_cast<const float2*>(&b4[j0]);

#pragma unroll
    for (int mf = 0; mf < 4; ++mf) {
#pragma unroll
        for (int rh = 0; rh < 2; ++rh) {
            const int row = bm + wm * 64 + mf * 16 + grp + rh * 8;
            const size_t rb = (size_t)row * Hsz + j0;
            const float2 cp = *reinterpret_cast<const float2*>(&Cprev[rb]);
            const float2 mk = *reinterpret_cast<const float2*>(&mask[rb]);
            float hv[2], cv[2];
#pragma unroll
            for (int e = 0; e < 2; ++e) {
                const int r = rh * 2 + e;
                float ft = sigmoidf_(acc[mf][0][r] + (e ? B1.y : B1.x));
                float it = sigmoidf_(acc[mf][1][r] + (e ? B2.y : B2.x));
                float ot = sigmoidf_(acc[mf][2][r] + (e ? B3.y : B3.x));
                float gt = tanhf   (acc[mf][3][r] + (e ? B4.y : B4.x));
                float ct = (e ? cp.y : cp.x) * ft + it * gt;
                hv[e] = ot * tanhf(ct) * (e ? mk.y : mk.x);
                cv[e] = ct;
            }
            *reinterpret_cast<float2*>(&out[rb]) = make_float2(hv[0], hv[1]);
            *reinterpret_cast<float2*>(&out[(size_t)Bsz * Hsz + rb]) = make_float2(cv[0], cv[1]);
        }
    }
}

// ---------------- launch ----------------
extern "C" void kernel_launch(void* const* d_in, const int* in_sizes, int n_in,
                              void* d_out, int out_size) {
    const float* X     = (const float*)d_in[0];
    const float* Hn    = (const float*)d_in[1];
    const float* Cprev = (const float*)d_in[2];
    const float* wi    = (const float*)d_in[3];
    const float* wf    = (const float*)d_in[4];
    const float* wo    = (const float*)d_in[5];
    const float* wc    = (const float*)d_in[6];
    const float* ui    = (const float*)d_in[7];
    const float* uf    = (const float*)d_in[8];
    const float* uo    = (const float*)d_in[9];
    const float* uc    = (const float*)d_in[10];
    const float* b1    = (const float*)d_in[11];
    const float* b2    = (const float*)d_in[12];
    const float* b3    = (const float*)d_in[13];
    const float* b4    = (const float*)d_in[14];
    const float* mask  = (const float*)d_in[15];
    float* out = (float*)d_out;

    conv_a_kernel<<<(Bsz * Ktot / 4) / 256, 256>>>(X, Hn);

    dim3 tb(32, 8);
    dim3 tg(Ktot / 32, Ntot / 32);
    conv_b_kernel<<<tg, tb>>>(wf, wi, wo, wc, uf, ui, uo, uc);

    static bool attr_set = false;
    if (!attr_set) {
        cudaFuncSetAttribute(gemm_kernel, cudaFuncAttributeMaxDynamicSharedMemorySize, GEMM_SMEM);
        attr_set = true;
    }
    dim3 gg(Ntot / BN, Bsz / BM);    // (16, 16) = 256 CTAs
    gemm_kernel<<<gg, 512, GEMM_SMEM>>>(Cprev, mask, b1, b2, b3, b4, out);
}

// round 5
// speedup vs baseline: 6.6504x; 1.6420x over previous
#include <cuda_runtime.h>
#include <cuda_fp16.h>
#include <cstdint>

#define Bsz 2048
#define Hsz 1024
#define Ktot 2048           // input K (1024) + hidden K (1024)
#define Ntot 4096           // 4 gates * 1024 (gate-interleaved bands of 32)

// ---------------- scratch (static device memory; no allocs) ----------------
__device__ unsigned short g_A[Bsz * Ktot];              // 8 MB  (fp16)
__device__ unsigned short g_B[(size_t)Ntot * Ktot];     // 16 MB (fp16, [n'][k])

// ---------------- helpers ----------------
__device__ __forceinline__ uint32_t smem_u32(const void* p) {
    uint32_t a;
    asm("{ .reg .u64 t; cvta.to.shared.u64 t, %1; cvt.u32.u64 %0, t; }" : "=r"(a) : "l"(p));
    return a;
}
__device__ __forceinline__ void cp_async16(uint32_t dst, const void* src) {
    asm volatile("cp.async.cg.shared.global [%0], [%1], 16;" :: "r"(dst), "l"(src) : "memory");
}
#define CP_COMMIT() asm volatile("cp.async.commit_group;" ::: "memory")
#define CP_WAIT2()  asm volatile("cp.async.wait_group 2;" ::: "memory")

__device__ __forceinline__ void ldsm4(uint32_t& r0, uint32_t& r1, uint32_t& r2, uint32_t& r3,
                                      uint32_t addr) {
    asm volatile("ldmatrix.sync.aligned.m8n8.x4.shared.b16 {%0,%1,%2,%3}, [%4];"
                 : "=r"(r0), "=r"(r1), "=r"(r2), "=r"(r3) : "r"(addr));
}
__device__ __forceinline__ void mma16816(float* d, const uint32_t* a, const uint32_t* b) {
    asm volatile(
        "mma.sync.aligned.m16n8k16.row.col.f32.f16.f16.f32 "
        "{%0,%1,%2,%3}, {%4,%5,%6,%7}, {%8,%9}, {%0,%1,%2,%3};"
        : "+f"(d[0]), "+f"(d[1]), "+f"(d[2]), "+f"(d[3])
        : "r"(a[0]), "r"(a[1]), "r"(a[2]), "r"(a[3]), "r"(b[0]), "r"(b[1]));
}

// ---------------- 1) convert A: [input | hidden] -> fp16 ----------------
__global__ void conv_a_kernel(const float* __restrict__ X, const float* __restrict__ Hn) {
    int idx = blockIdx.x * blockDim.x + threadIdx.x;     // one float4
    int e0   = idx * 4;
    int col4 = e0 & (Ktot - 1);
    int row  = e0 >> 11;
    const float* src = (col4 < Hsz) ? &X[row * Hsz + col4] : &Hn[row * Hsz + col4 - Hsz];
    float4 v = *reinterpret_cast<const float4*>(src);
    unsigned short h[4];
    h[0] = __half_as_ushort(__float2half_rn(v.x));
    h[1] = __half_as_ushort(__float2half_rn(v.y));
    h[2] = __half_as_ushort(__float2half_rn(v.z));
    h[3] = __half_as_ushort(__float2half_rn(v.w));
    *reinterpret_cast<uint2*>(&g_A[e0]) = *reinterpret_cast<uint2*>(h);
}

// ------ 2) transpose + convert weights -> B [n'][k] fp16, gate-interleaved ----
// n' = (j>>3)*32 + g*8 + (j&7)   for original gate g, hidden col j
__global__ void conv_b_kernel(const float* wf, const float* wi, const float* wo, const float* wc,
                              const float* uf, const float* ui, const float* uo, const float* uc) {
    __shared__ float tile[64][65];     // [k][n]
    const float* srcs[8] = {wf, wi, wo, wc, uf, ui, uo, uc};
    int k0 = blockIdx.x * 64;          // 0..2047
    int n0 = blockIdx.y * 64;          // 0..4095 (original gate-major space)
    int g  = n0 >> 10;
    const float* W = srcs[(k0 < Hsz ? 0 : 4) + g];
    int kk = k0 & (Hsz - 1);
    int nn = n0 & (Hsz - 1);
    int tx = threadIdx.x, ty = threadIdx.y;  // 64 x 8
#pragma unroll
    for (int j = 0; j < 8; ++j)
        tile[ty + j * 8][tx] = W[(size_t)(kk + ty + j * 8) * Hsz + nn + tx];
    __syncthreads();
#pragma unroll
    for (int j = 0; j < 8; ++j) {
        int jn = nn + ty + j * 8;            // hidden col
        int np = ((jn >> 3) << 5) + (g << 3) + (jn & 7);
        g_B[(size_t)np * Ktot + k0 + tx] =
            __half_as_ushort(__float2half_rn(tile[tx][ty + j * 8]));
    }
}

// ------ 3) mma.sync single-pass fp16 GEMM + fused LSTM epilogue ------
#define BM 128
#define BN 128
#define BK 32
#define NSTAGE 4
#define A_ST_BYTES (BM * BK * 2)             // 8192
#define B_ST_BYTES (BN * BK * 2)             // 8192
#define STAGE_BYTES (A_ST_BYTES + B_ST_BYTES)  // 16384
#define GEMM_SMEM (NSTAGE * STAGE_BYTES)     // 65536
#define NCHUNK 64                             // 2048 / 32

__device__ __forceinline__ uint32_t swz(uint32_t base, int r, int c) {
    return base + r * 64 + (((uint32_t)(c ^ ((r >> 1) & 3))) << 4);
}
__device__ __forceinline__ float sigmoidf_(float x) { return 1.0f / (1.0f + expf(-x)); }

__global__ void __launch_bounds__(256, 2)
gemm_kernel(const float* __restrict__ Cprev, const float* __restrict__ mask,
            const float* __restrict__ b1, const float* __restrict__ b2,
            const float* __restrict__ b3, const float* __restrict__ b4,
            float* __restrict__ out) {
    extern __shared__ char smem[];
    const uint32_t sb = smem_u32(smem);
    const int tid  = threadIdx.x;
    const int wid  = tid >> 5;
    const int lane = tid & 31;
    const int wm = wid >> 2;       // 0..1  (M, 64 each)
    const int wn = wid & 3;        // 0..3  (N, 32 each)
    const int bm = blockIdx.y * BM;
    const int bn = blockIdx.x * BN;

    float acc[4][4][4];
#pragma unroll
    for (int mf = 0; mf < 4; ++mf)
#pragma unroll
        for (int nf = 0; nf < 4; ++nf)
#pragma unroll
            for (int r = 0; r < 4; ++r) acc[mf][nf][r] = 0.0f;

    // load indices (16B chunks): A 512, B 512 -> 2 per thread per tensor
    const int r0i = tid >> 2, c0i = tid & 3;             // chunk g = tid
    const int r1i = (tid + 256) >> 2, c1i = tid & 3;     // chunk g = tid + 256

    auto load_chunk = [&](int c) {
        const uint32_t st = (uint32_t)(c & (NSTAGE - 1)) * STAGE_BYTES;
        const uint32_t sA = sb + st;
        const uint32_t sB = sA + A_ST_BYTES;
        const char* Ag = (const char*)g_A + ((size_t)bm * Ktot + (size_t)c * BK) * 2;
        const char* Bg = (const char*)g_B + ((size_t)bn * Ktot + (size_t)c * BK) * 2;
        cp_async16(swz(sA, r0i, c0i), Ag + (size_t)r0i * (Ktot * 2) + c0i * 16);
        cp_async16(swz(sA, r1i, c1i), Ag + (size_t)r1i * (Ktot * 2) + c1i * 16);
        cp_async16(swz(sB, r0i, c0i), Bg + (size_t)r0i * (Ktot * 2) + c0i * 16);
        cp_async16(swz(sB, r1i, c1i), Bg + (size_t)r1i * (Ktot * 2) + c1i * 16);
        CP_COMMIT();
    };

    load_chunk(0); load_chunk(1); load_chunk(2);

    const int a_row = wm * 64 + (lane & 15);
    const int a_cb  = (lane >> 4) & 1;
    const int b_row = wn * 32 + ((lane >> 4) & 1) * 8 + (lane & 7);
    const int b_cb  = (lane >> 3) & 1;

    for (int c = 0; c < NCHUNK; ++c) {
        CP_WAIT2();
        __syncthreads();
        const uint32_t st = (uint32_t)(c & (NSTAGE - 1)) * STAGE_BYTES;
        const uint32_t sA = sb + st;
        const uint32_t sB = sA + A_ST_BYTES;

#pragma unroll
        for (int ks = 0; ks < 2; ++ks) {
            uint32_t bf[2][4];
#pragma unroll
            for (int nfp = 0; nfp < 2; ++nfp)
                ldsm4(bf[nfp][0], bf[nfp][1], bf[nfp][2], bf[nfp][3],
                      swz(sB, b_row + nfp * 16, ks * 2 + b_cb));
            uint32_t af[4][4];
#pragma unroll
            for (int mf = 0; mf < 4; ++mf)
                ldsm4(af[mf][0], af[mf][1], af[mf][2], af[mf][3],
                      swz(sA, a_row + mf * 16, ks * 2 + a_cb));
#pragma unroll
            for (int mf = 0; mf < 4; ++mf)
#pragma unroll
                for (int nf = 0; nf < 4; ++nf)
                    mma16816(acc[mf][nf], af[mf], &bf[nf >> 1][(nf & 1) * 2]);
        }
        __syncthreads();
        if (c + NSTAGE - 1 < NCHUNK) load_chunk(c + NSTAGE - 1);
        else CP_COMMIT();
    }

    // ---- fused LSTM epilogue ----
    // warp band: n' in [bn + wn*32, +32) -> hidden octet j0, nf = gate
    const int grp = lane >> 2, tig = lane & 3;
    const int j0 = ((bn >> 5) + wn) * 8 + tig * 2;   // hidden col of acc pair
    const float2 B1 = *reinterpret_cast<const float2*>(&b1[j0]);
    const float2 B2 = *reinterpret_cast<const float2*>(&b2[j0]);
    const float2 B3 = *reinterpret_cast<const float2*>(&b3[j0]);
    const float2 B4 = *reinterpret_cast<const float2*>(&b4[j0]);

#pragma unroll
    for (int mf = 0; mf < 4; ++mf) {
#pragma unroll
        for (int rh = 0; rh < 2; ++rh) {
            const int row = bm + wm * 64 + mf * 16 + grp + rh * 8;
            const size_t rb = (size_t)row * Hsz + j0;
            const float2 cp = *reinterpret_cast<const float2*>(&Cprev[rb]);
            const float2 mk = *reinterpret_cast<const float2*>(&mask[rb]);
            float hv[2], cv[2];
#pragma unroll
            for (int e = 0; e < 2; ++e) {
                const int r = rh * 2 + e;
                float ft = sigmoidf_(acc[mf][0][r] + (e ? B1.y : B1.x));
                float it = sigmoidf_(acc[mf][1][r] + (e ? B2.y : B2.x));
                float ot = sigmoidf_(acc[mf][2][r] + (e ? B3.y : B3.x));
                float gt = tanhf   (acc[mf][3][r] + (e ? B4.y : B4.x));
                float ct = (e ? cp.y : cp.x) * ft + it * gt;
                hv[e] = ot * tanhf(ct) * (e ? mk.y : mk.x);
                cv[e] = ct;
            }
            *reinterpret_cast<float2*>(&out[rb]) = make_float2(hv[0], hv[1]);
            *reinterpret_cast<float2*>(&out[(size_t)Bsz * Hsz + rb]) = make_float2(cv[0], cv[1]);
        }
    }
}

// ---------------- launch ----------------
extern "C" void kernel_launch(void* const* d_in, const int* in_sizes, int n_in,
                              void* d_out, int out_size) {
    const float* X     = (const float*)d_in[0];
    const float* Hn    = (const float*)d_in[1];
    const float* Cprev = (const float*)d_in[2];
    const float* wi    = (const float*)d_in[3];
    const float* wf    = (const float*)d_in[4];
    const float* wo    = (const float*)d_in[5];
    const float* wc    = (const float*)d_in[6];
    const float* ui    = (const float*)d_in[7];
    const float* uf    = (const float*)d_in[8];
    const float* uo    = (const float*)d_in[9];
    const float* uc    = (const float*)d_in[10];
    const float* b1    = (const float*)d_in[11];
    const float* b2    = (const float*)d_in[12];
    const float* b3    = (const float*)d_in[13];
    const float* b4    = (const float*)d_in[14];
    const float* mask  = (const float*)d_in[15];
    float* out = (float*)d_out;

    conv_a_kernel<<<(Bsz * Ktot / 4) / 256, 256>>>(X, Hn);

    dim3 tb(64, 8);
    dim3 tg(Ktot / 64, Ntot / 64);     // (32, 64)
    conv_b_kernel<<<tg, tb>>>(wf, wi, wo, wc, uf, ui, uo, uc);

    static bool attr_set = false;
    if (!attr_set) {
        cudaFuncSetAttribute(gemm_kernel, cudaFuncAttributeMaxDynamicSharedMemorySize, GEMM_SMEM);
        attr_set = true;
    }
    dim3 gg(Ntot / BN, Bsz / BM);      // (32, 16) = 512 CTAs
    gemm_kernel<<<gg, 256, GEMM_SMEM>>>(Cprev, mask, b1, b2, b3, b4, out);
}

// round 7
// speedup vs baseline: 7.3436x; 1.1042x over previous
#include <cuda_runtime.h>
#include <cuda_fp16.h>
#include <cstdint>

#define Bsz 2048
#define Hsz 1024
#define Ktot 2048           // input K (1024) + hidden K (1024)
#define Ntot 4096           // 4 gates * 1024 (gate-interleaved bands of 32)

// ---------------- scratch (static device memory; no allocs) ----------------
__device__ unsigned short g_A[Bsz * Ktot];              // 8 MB  (fp16)
__device__ unsigned short g_B[(size_t)Ntot * Ktot];     // 16 MB (fp16, [n'][k])

// ---------------- helpers ----------------
__device__ __forceinline__ uint32_t smem_u32(const void* p) {
    uint32_t a;
    asm("{ .reg .u64 t; cvta.to.shared.u64 t, %1; cvt.u32.u64 %0, t; }" : "=r"(a) : "l"(p));
    return a;
}
__device__ __forceinline__ void cp_async16(uint32_t dst, const void* src) {
    asm volatile("cp.async.cg.shared.global [%0], [%1], 16;" :: "r"(dst), "l"(src) : "memory");
}
#define CP_COMMIT() asm volatile("cp.async.commit_group;" ::: "memory")
#define CP_WAIT1()  asm volatile("cp.async.wait_group 1;" ::: "memory")

__device__ __forceinline__ void ldsm4(uint32_t& r0, uint32_t& r1, uint32_t& r2, uint32_t& r3,
                                      uint32_t addr) {
    asm volatile("ldmatrix.sync.aligned.m8n8.x4.shared.b16 {%0,%1,%2,%3}, [%4];"
                 : "=r"(r0), "=r"(r1), "=r"(r2), "=r"(r3) : "r"(addr));
}
__device__ __forceinline__ void mma16816(float* d, const uint32_t* a, const uint32_t* b) {
    asm volatile(
        "mma.sync.aligned.m16n8k16.row.col.f32.f16.f16.f32 "
        "{%0,%1,%2,%3}, {%4,%5,%6,%7}, {%8,%9}, {%0,%1,%2,%3};"
        : "+f"(d[0]), "+f"(d[1]), "+f"(d[2]), "+f"(d[3])
        : "r"(a[0]), "r"(a[1]), "r"(a[2]), "r"(a[3]), "r"(b[0]), "r"(b[1]));
}

// ---------------- 1) convert A: [input | hidden] -> fp16 ----------------
__global__ void conv_a_kernel(const float* __restrict__ X, const float* __restrict__ Hn) {
    int idx = blockIdx.x * blockDim.x + threadIdx.x;     // one float4
    int e0   = idx * 4;
    int col4 = e0 & (Ktot - 1);
    int row  = e0 >> 11;
    const float* src = (col4 < Hsz) ? &X[row * Hsz + col4] : &Hn[row * Hsz + col4 - Hsz];
    float4 v = *reinterpret_cast<const float4*>(src);
    unsigned short h[4];
    h[0] = __half_as_ushort(__float2half_rn(v.x));
    h[1] = __half_as_ushort(__float2half_rn(v.y));
    h[2] = __half_as_ushort(__float2half_rn(v.z));
    h[3] = __half_as_ushort(__float2half_rn(v.w));
    *reinterpret_cast<uint2*>(&g_A[e0]) = *reinterpret_cast<uint2*>(h);
}

// ------ 2) transpose + convert weights -> B [n'][k] fp16, gate-interleaved ----
// n' = (j>>3)*32 + g*8 + (j&7)   for original gate g, hidden col j
__global__ void conv_b_kernel(const float* wf, const float* wi, const float* wo, const float* wc,
                              const float* uf, const float* ui, const float* uo, const float* uc) {
    __shared__ float tile[64][65];     // [k][n]
    const float* srcs[8] = {wf, wi, wo, wc, uf, ui, uo, uc};
    int k0 = blockIdx.x * 64;          // 0..2047
    int n0 = blockIdx.y * 64;          // 0..4095 (original gate-major space)
    int g  = n0 >> 10;
    const float* W = srcs[(k0 < Hsz ? 0 : 4) + g];
    int kk = k0 & (Hsz - 1);
    int nn = n0 & (Hsz - 1);
    int tx = threadIdx.x, ty = threadIdx.y;  // 64 x 8
#pragma unroll
    for (int j = 0; j < 8; ++j)
        tile[ty + j * 8][tx] = W[(size_t)(kk + ty + j * 8) * Hsz + nn + tx];
    __syncthreads();
#pragma unroll
    for (int j = 0; j < 8; ++j) {
        int jn = nn + ty + j * 8;            // hidden col
        int np = ((jn >> 3) << 5) + (g << 3) + (jn & 7);
        g_B[(size_t)np * Ktot + k0 + tx] =
            __half_as_ushort(__float2half_rn(tile[tx][ty + j * 8]));
    }
}

// ------ 3) mma.sync single-pass fp16 GEMM + fused LSTM epilogue ------
#define BM 128
#define BN 128
#define BK 64
#define NSTAGE 3
#define A_ST_BYTES (BM * BK * 2)               // 16384
#define STAGE_BYTES (2 * A_ST_BYTES)           // 32768
#define GEMM_SMEM (NSTAGE * STAGE_BYTES)       // 98304
#define NCHUNK 32                               // 2048 / 64

// 128-byte smem rows (8 x 16B chunks); SW128 swizzle: chunk ^= row&7.
// Conflict-free for cp.async row stores and ldmatrix column reads.
__device__ __forceinline__ uint32_t swz(uint32_t base, int r, int c) {
    return base + r * 128 + (((uint32_t)(c ^ (r & 7))) << 4);
}
__device__ __forceinline__ float sigmoidf_(float x) { return 1.0f / (1.0f + expf(-x)); }

__global__ void __launch_bounds__(256, 2)
gemm_kernel(const float* __restrict__ Cprev, const float* __restrict__ mask,
            const float* __restrict__ b1, const float* __restrict__ b2,
            const float* __restrict__ b3, const float* __restrict__ b4,
            float* __restrict__ out) {
    extern __shared__ char smem[];
    const uint32_t sb = smem_u32(smem);
    const int tid  = threadIdx.x;
    const int wid  = tid >> 5;
    const int lane = tid & 31;
    const int wm = wid >> 2;       // 0..1  (M, 64 each)
    const int wn = wid & 3;        // 0..3  (N, 32 each)
    const int bm = blockIdx.y * BM;
    const int bn = blockIdx.x * BN;

    float acc[4][4][4];
#pragma unroll
    for (int mf = 0; mf < 4; ++mf)
#pragma unroll
        for (int nf = 0; nf < 4; ++nf)
#pragma unroll
            for (int r = 0; r < 4; ++r) acc[mf][nf][r] = 0.0f;

    // per-thread load map: each tensor is 128 rows x 8 chunks = 1024 chunks,
    // 256 threads -> 4 chunks/thread/tensor (8 cp.async per chunk load)
    const int lr = tid >> 3;          // row 0..31 (+32*i)
    const int lc = tid & 7;           // chunk col 0..7

    auto load_chunk = [&](int c, int st) {
        const uint32_t sA = sb + (uint32_t)st * STAGE_BYTES;
        const uint32_t sB = sA + A_ST_BYTES;
        const char* Ag = (const char*)g_A + ((size_t)bm * Ktot + (size_t)c * BK) * 2;
        const char* Bg = (const char*)g_B + ((size_t)bn * Ktot + (size_t)c * BK) * 2;
#pragma unroll
        for (int i = 0; i < 4; ++i) {
            const int r = lr + i * 32;
            cp_async16(swz(sA, r, lc), Ag + (size_t)r * (Ktot * 2) + lc * 16);
        }
#pragma unroll
        for (int i = 0; i < 4; ++i) {
            const int r = lr + i * 32;
            cp_async16(swz(sB, r, lc), Bg + (size_t)r * (Ktot * 2) + lc * 16);
        }
        CP_COMMIT();
    };

    load_chunk(0, 0);
    load_chunk(1, 1);

    const int a_row = wm * 64 + (lane & 15);
    const int a_cb  = (lane >> 4) & 1;
    const int b_row = wn * 32 + ((lane >> 4) & 1) * 8 + (lane & 7);
    const int b_cb  = (lane >> 3) & 1;

    int rd = 0;                        // stage holding chunk c
    for (int c = 0; c < NCHUNK; ++c) {
        CP_WAIT1();
        __syncthreads();
        // issue next load first (into stage rd-1 mod 3, no longer read by anyone)
        if (c + 2 < NCHUNK) {
            const int wr = (rd == 0) ? 2 : rd - 1;
            load_chunk(c + 2, wr);
        } else {
            CP_COMMIT();
        }

        const uint32_t sA = sb + (uint32_t)rd * STAGE_BYTES;
        const uint32_t sB = sA + A_ST_BYTES;
#pragma unroll
        for (int ks = 0; ks < 4; ++ks) {
            uint32_t bf[2][4];
#pragma unroll
            for (int nfp = 0; nfp < 2; ++nfp)
                ldsm4(bf[nfp][0], bf[nfp][1], bf[nfp][2], bf[nfp][3],
                      swz(sB, b_row + nfp * 16, ks * 2 + b_cb));
            uint32_t af[4][4];
#pragma unroll
            for (int mf = 0; mf < 4; ++mf)
                ldsm4(af[mf][0], af[mf][1], af[mf][2], af[mf][3],
                      swz(sA, a_row + mf * 16, ks * 2 + a_cb));
#pragma unroll
            for (int mf = 0; mf < 4; ++mf)
#pragma unroll
                for (int nf = 0; nf < 4; ++nf)
                    mma16816(acc[mf][nf], af[mf], &bf[nf >> 1][(nf & 1) * 2]);
        }
        rd = (rd == 2) ? 0 : rd + 1;
    }

    // ---- fused LSTM epilogue ----
    // warp band: n' in [bn + wn*32, +32) -> hidden octet j0, nf = gate
    const int grp = lane >> 2, tig = lane & 3;
    const int j0 = ((bn >> 5) + wn) * 8 + tig * 2;   // hidden col of acc pair
    const float2 B1 = *reinterpret_cast<const float2*>(&b1[j0]);
    const float2 B2 = *reinterpret_cast<const float2*>(&b2[j0]);
    const float2 B3 = *reinterpret_cast<const float2*>(&b3[j0]);
    const float2 B4 = *reinterpret_cast<const float2*>(&b4[j0]);

#pragma unroll
    for (int mf = 0; mf < 4; ++mf) {
#pragma unroll
        for (int rh = 0; rh < 2; ++rh) {
            const int row = bm + wm * 64 + mf * 16 + grp + rh * 8;
            const size_t rb = (size_t)row * Hsz + j0;
            const float2 cp = *reinterpret_cast<const float2*>(&Cprev[rb]);
            const float2 mk = *reinterpret_cast<const float2*>(&mask[rb]);
            float hv[2], cv[2];
#pragma unroll
            for (int e = 0; e < 2; ++e) {
                const int r = rh * 2 + e;
                float ft = sigmoidf_(acc[mf][0][r] + (e ? B1.y : B1.x));
                float it = sigmoidf_(acc[mf][1][r] + (e ? B2.y : B2.x));
                float ot = sigmoidf_(acc[mf][2][r] + (e ? B3.y : B3.x));
                float gt = tanhf   (acc[mf][3][r] + (e ? B4.y : B4.x));
                float ct = (e ? cp.y : cp.x) * ft + it * gt;
                hv[e] = ot * tanhf(ct) * (e ? mk.y : mk.x);
                cv[e] = ct;
            }
            *reinterpret_cast<float2*>(&out[rb]) = make_float2(hv[0], hv[1]);
            *reinterpret_cast<float2*>(&out[(size_t)Bsz * Hsz + rb]) = make_float2(cv[0], cv[1]);
        }
    }
}

// ---------------- launch ----------------
extern "C" void kernel_launch(void* const* d_in, const int* in_sizes, int n_in,
                              void* d_out, int out_size) {
    const float* X     = (const float*)d_in[0];
    const float* Hn    = (const float*)d_in[1];
    const float* Cprev = (const float*)d_in[2];
    const float* wi    = (const float*)d_in[3];
    const float* wf    = (const float*)d_in[4];
    const float* wo    = (const float*)d_in[5];
    const float* wc    = (const float*)d_in[6];
    const float* ui    = (const float*)d_in[7];
    const float* uf    = (const float*)d_in[8];
    const float* uo    = (const float*)d_in[9];
    const float* uc    = (const float*)d_in[10];
    const float* b1    = (const float*)d_in[11];
    const float* b2    = (const float*)d_in[12];
    const float* b3    = (const float*)d_in[13];
    const float* b4    = (const float*)d_in[14];
    const float* mask  = (const float*)d_in[15];
    float* out = (float*)d_out;

    conv_a_kernel<<<(Bsz * Ktot / 4) / 256, 256>>>(X, Hn);

    dim3 tb(64, 8);
    dim3 tg(Ktot / 64, Ntot / 64);     // (32, 64)
    conv_b_kernel<<<tg, tb>>>(wf, wi, wo, wc, uf, ui, uo, uc);

    static bool attr_set = false;
    if (!attr_set) {
        cudaFuncSetAttribute(gemm_kernel, cudaFuncAttributeMaxDynamicSharedMemorySize, GEMM_SMEM);
        attr_set = true;
    }
    dim3 gg(Ntot / BN, Bsz / BM);      // (32, 16) = 512 CTAs
    gemm_kernel<<<gg, 256, GEMM_SMEM>>>(Cprev, mask, b1, b2, b3, b4, out);
}